// round 6
// baseline (speedup 1.0000x reference)
#include <cuda_runtime.h>
#include <cuda_fp16.h>
#include <math.h>
#include <stdint.h>

// ---------------- problem constants ----------------
#define DIM     48
#define QKVC    144
#define H_IMG   256
#define W_IMG   256
#define HW      65536
#define NH      8
#define HC      96
#define OHW     66
#define NP      4356
#define NPP     4480         // padded to 35*128
#define PADU    4
#define LOG2E   1.44269504f
#define VGAIN   2048.0f

// ---------------- scratch ----------------
__device__ float  g_qkv [QKVC * HW];
__device__ float  g_dw  [QKVC * HW];
__device__ __align__(16) __half g_qt[NH * NPP * HC];   // normalized q, [h][n][c]
__device__ __align__(16) __half g_kt[NH * NPP * HC];   // normalized k, [h][m][c]
__device__ __align__(16) __half g_vh[NH * HC * NPP];   // Vs = C*v/rowsum (pad 0)
__device__ __align__(16) __half g_E [(size_t)NH * NPP * NPP]; // E^T: [h][m][n]
__device__ float  g_rowsum[NH * NPP];
__device__ float  g_o   [NH * HC * NPP];

__device__ __forceinline__ void cpa16(void* dst, const void* src) {
    unsigned d = (unsigned)__cvta_generic_to_shared(dst);
    asm volatile("cp.async.cg.shared.global [%0], [%1], 16;\n" :: "r"(d), "l"(src));
}
#define CP_COMMIT() asm volatile("cp.async.commit_group;\n")
#define CP_WAIT0()  asm volatile("cp.async.wait_group 0;\n")
#define CP_WAIT1()  asm volatile("cp.async.wait_group 1;\n")

// ================= 1) qkv 1x1 projection ===================================
__global__ __launch_bounds__(256) void k_qkv_proj(const float* __restrict__ x,
                                                  const float* __restrict__ w) {
    __shared__ float xs[DIM][256];
    int t = threadIdx.x;
    int p0 = blockIdx.x * 256;
#pragma unroll
    for (int c = 0; c < DIM; c++) xs[c][t] = x[c * HW + p0 + t];
    __syncthreads();
    for (int o = 0; o < QKVC; o++) {
        float acc = 0.f;
#pragma unroll
        for (int c = 0; c < DIM; c++) acc += __ldg(&w[o * DIM + c]) * xs[c][t];
        g_qkv[o * HW + p0 + t] = acc;
    }
}

// ================= 2) depthwise 3x3 ========================================
__global__ __launch_bounds__(256) void k_dwconv(const float* __restrict__ wdw) {
    int idx = blockIdx.x * 256 + threadIdx.x;
    int ch = idx >> 16;
    int p  = idx & 65535;
    int y = p >> 8, x = p & 255;
    const float* wv = wdw + ch * 9;
    const float* in = g_qkv + ch * HW;
    float acc = 0.f;
#pragma unroll
    for (int di = 0; di < 3; di++) {
        int yy = y + di - 1;
        if ((unsigned)yy >= H_IMG) continue;
#pragma unroll
        for (int dj = 0; dj < 3; dj++) {
            int xx = x + dj - 1;
            if ((unsigned)xx >= W_IMG) continue;
            acc += wv[di * 3 + dj] * in[yy * W_IMG + xx];
        }
    }
    g_dw[idx] = acc;
}

// ================= 3) fused unfold + L2-norm -> fp16 [h][n][c] =============
__global__ __launch_bounds__(256) void k_unfold_l2() {
    int warp = blockIdx.x * 8 + (threadIdx.x >> 5);   // over 2*NH*NP
    int lane = threadIdx.x & 31;
    int n = warp % NP;
    int r = warp / NP;
    int h = r & 7;
    int which = r >> 3;
    int i = n / OHW, j = n - i * OHW;
    float v[3];
#pragma unroll
    for (int l = 0; l < 3; l++) {
        int cd = lane + 32 * l;
        int row = h * HC + cd;
        int c = row >> 4;
        int kk = row & 15;
        int ki = kk >> 2, kj = kk & 3;
        int y = 4 * i + ki - PADU;
        int x = 4 * j + kj - PADU;
        v[l] = 0.f;
        if ((unsigned)y < H_IMG && (unsigned)x < W_IMG)
            v[l] = g_dw[(which * DIM + c) * HW + y * W_IMG + x];
    }
    float ss = v[0] * v[0] + v[1] * v[1] + v[2] * v[2];
#pragma unroll
    for (int o = 16; o > 0; o >>= 1) ss += __shfl_xor_sync(0xffffffffu, ss, o);
    float s = 1.f / fmaxf(sqrtf(ss), 1e-12f);
    __half* dst = ((which == 0) ? g_qt : g_kt) + ((size_t)h * NPP + n) * HC;
    dst[lane]      = __float2half_rn(v[0] * s);
    dst[lane + 32] = __float2half_rn(v[1] * s);
    dst[lane + 64] = __float2half_rn(v[2] * s);
}

// ================= 4) zero rowsums =========================================
__global__ __launch_bounds__(256) void k_zero_rowsum() {
    int i = blockIdx.x * 256 + threadIdx.x;   // 8*NPP exact
    g_rowsum[i] = 0.f;
}

// ================= 5) GEMM1: E^T[m][n] = exp(t*(K_m.Q_n)-|t|), + rowsum ====
// 128(m) x 128(n), K=96 single shot. Epilogue: exp -> stage smem -> coalesced
// fp16 store of E^T + parallel column sums (over valid m) -> global atomic.
#define SA1 104
#define SE1 136
__global__ __launch_bounds__(256, 2) void k_gemm_qk(const float* __restrict__ temp) {
    extern __shared__ __half sm[];
    __half* As = sm;                 // [128][SA1]  K rows (m)
    __half* Bs = sm + 128 * SA1;     // [128][SA1]  Q rows (n)
    __shared__ float colsum[128];
    int h = blockIdx.z;
    const __half* A = g_kt + (size_t)h * NPP * HC;
    const __half* B = g_qt + (size_t)h * NPP * HC;
    int bm0 = blockIdx.y * 128;
    int bn0 = blockIdx.x * 128;
    int tid = threadIdx.x;
    if (tid < 128) colsum[tid] = 0.f;

#pragma unroll
    for (int l = 0; l < 6; l++) {
        int v = tid + l * 256;          // < 1536
        int r = v / 12, c = v % 12;
        cpa16(&As[r * SA1 + c * 8], A + (size_t)(bm0 + r) * HC + c * 8);
        cpa16(&Bs[r * SA1 + c * 8], B + (size_t)(bn0 + r) * HC + c * 8);
    }
    CP_COMMIT();
    CP_WAIT0();
    __syncthreads();

    int warp = tid >> 5, lane = tid & 31;
    int wm = warp >> 2, wn = warp & 3;      // 2(m) x 4(n)
    int g = lane >> 3, rr = lane & 7;

    float acc[4][4][4];
#pragma unroll
    for (int i = 0; i < 4; i++)
#pragma unroll
        for (int j = 0; j < 4; j++)
#pragma unroll
            for (int q = 0; q < 4; q++) acc[i][j][q] = 0.f;

    unsigned sA = (unsigned)__cvta_generic_to_shared(As);
    unsigned sB = (unsigned)__cvta_generic_to_shared(Bs);

#pragma unroll
    for (int kk = 0; kk < 6; kk++) {
        unsigned a[4][4], b[4][2];
#pragma unroll
        for (int i = 0; i < 4; i++) {
            int row = wm * 64 + i * 16 + rr + (g & 1) * 8;
            int ko  = kk * 16 + (g >> 1) * 8;
            unsigned ad = sA + (row * SA1 + ko) * 2;
            asm volatile("ldmatrix.sync.aligned.m8n8.x4.shared.b16 {%0,%1,%2,%3}, [%4];"
                         : "=r"(a[i][0]), "=r"(a[i][1]), "=r"(a[i][2]), "=r"(a[i][3])
                         : "r"(ad));
        }
#pragma unroll
        for (int jp = 0; jp < 2; jp++) {
            int col = wn * 32 + (jp * 2 + (g >> 1)) * 8 + rr;
            int ko  = kk * 16 + (g & 1) * 8;
            unsigned ad = sB + (col * SA1 + ko) * 2;
            asm volatile("ldmatrix.sync.aligned.m8n8.x4.shared.b16 {%0,%1,%2,%3}, [%4];"
                         : "=r"(b[jp * 2][0]), "=r"(b[jp * 2][1]),
                           "=r"(b[jp * 2 + 1][0]), "=r"(b[jp * 2 + 1][1])
                         : "r"(ad));
        }
#pragma unroll
        for (int i = 0; i < 4; i++)
#pragma unroll
            for (int j = 0; j < 4; j++) {
                asm volatile(
                    "mma.sync.aligned.m16n8k16.row.col.f32.f16.f16.f32 "
                    "{%0,%1,%2,%3},{%4,%5,%6,%7},{%8,%9},{%0,%1,%2,%3};"
                    : "+f"(acc[i][j][0]), "+f"(acc[i][j][1]),
                      "+f"(acc[i][j][2]), "+f"(acc[i][j][3])
                    : "r"(a[i][0]), "r"(a[i][1]), "r"(a[i][2]), "r"(a[i][3]),
                      "r"(b[j][0]), "r"(b[j][1]));
            }
    }
    __syncthreads();   // done with As/Bs; reuse smem for staged E tile

    float t  = __ldg(&temp[h]);
    float tl = t * LOG2E;
    float ab = fabsf(t) * LOG2E;

    __half* Es = sm;   // [128][SE1]
#pragma unroll
    for (int i = 0; i < 4; i++) {
        int r0 = wm * 64 + i * 16 + (lane >> 2);
#pragma unroll
        for (int j = 0; j < 4; j++) {
            int c0 = wn * 32 + j * 8 + 2 * (lane & 3);
            float e0 = exp2f(acc[i][j][0] * tl - ab);
            float e1 = exp2f(acc[i][j][1] * tl - ab);
            float e2 = exp2f(acc[i][j][2] * tl - ab);
            float e3 = exp2f(acc[i][j][3] * tl - ab);
            *reinterpret_cast<__half2*>(&Es[r0 * SE1 + c0]) = __floats2half2_rn(e0, e1);
            *reinterpret_cast<__half2*>(&Es[(r0 + 8) * SE1 + c0]) = __floats2half2_rn(e2, e3);
        }
    }
    __syncthreads();

    // coalesced write of E^T tile
    __half* Eh = g_E + (size_t)h * NPP * NPP;
#pragma unroll
    for (int l = 0; l < 8; l++) {
        int v = tid + l * 256;          // < 2048
        int r = v >> 4, c8 = v & 15;
        reinterpret_cast<uint4*>(Eh + (size_t)(bm0 + r) * NPP + bn0)[c8] =
            reinterpret_cast<uint4*>(&Es[r * SE1])[c8];
    }

    // parallel column sums over valid m (two threads per column)
    int mlim = NP - bm0; if (mlim > 128) mlim = 128;
    {
        int col = tid & 127;
        int half = tid >> 7;            // 0 or 1
        int m0 = half * 64;
        int m1 = m0 + 64; if (m1 > mlim) m1 = mlim;
        float s = 0.f;
        for (int m = m0; m < m1; m++) s += __half2float(Es[m * SE1 + col]);
        if (s != 0.f) atomicAdd(&colsum[col], s);
    }
    __syncthreads();
    if (tid < 128) atomicAdd(&g_rowsum[h * NPP + bn0 + tid], colsum[tid]);
}

// ================= 6) fused unfold_v + scale: Vs = C*v/rowsum -> fp16 ======
__global__ __launch_bounds__(256) void k_vscale() {
    int t = blockIdx.x * 256 + threadIdx.x;  // over NH*HC*NP (exact)
    int n  = t % NP;
    int r  = t / NP;
    int cd = r % HC;
    int h  = r / HC;
    int row = h * HC + cd;
    int c  = row >> 4;
    int kk = row & 15;
    int ki = kk >> 2, kj = kk & 3;
    int i = n / OHW, j = n - i * OHW;
    int y = 4 * i + ki - PADU;
    int x = 4 * j + kj - PADU;
    float val = 0.f;
    if ((unsigned)y < H_IMG && (unsigned)x < W_IMG)
        val = g_dw[(2 * DIM + c) * HW + y * W_IMG + x];
    g_vh[(size_t)(h * HC + cd) * NPP + n] =
        __float2half_rn(val * VGAIN / g_rowsum[h * NPP + n]);
}

// ================= 7) GEMM2: out[c][m] = (1/C) sum_n Vs[c][n] E^T[m][n] ====
// 96(c) x 128(m) tile, k-chunk 64, 3-stage cp.async pipeline, 1 sync/iter.
#define SA2 72
#define NCH 69      // 69*64 = 4416 >= NP; last all-zero chunk skipped
__global__ __launch_bounds__(256, 2) void k_gemm_av() {
    extern __shared__ __half sm2[];
    const int STG = (96 + 128) * SA2;     // halves per stage
    __half* Ast[3] = { sm2,            sm2 + STG,            sm2 + 2 * STG };
    __half* Bst[3] = { sm2 + 96 * SA2, sm2 + STG + 96 * SA2, sm2 + 2 * STG + 96 * SA2 };

    int h = blockIdx.y;
    const __half* A = g_vh + (size_t)h * HC * NPP;
    const __half* B = g_E  + (size_t)h * NPP * NPP;
    int bm0 = blockIdx.x * 128;
    int tid = threadIdx.x;
    int warp = tid >> 5, lane = tid & 31;
    int wc = warp >> 2, wm = warp & 3;
    int g = lane >> 3, rr = lane & 7;

    auto load_chunk = [&](int stg, int n0) {
        __half* Ad = Ast[stg];
        __half* Bd = Bst[stg];
#pragma unroll
        for (int l = 0; l < 3; l++) {
            int v = tid + l * 256;
            int r = v >> 3, c8 = v & 7;
            cpa16(&Ad[r * SA2 + c8 * 8], A + (size_t)r * NPP + n0 + c8 * 8);
        }
#pragma unroll
        for (int l = 0; l < 4; l++) {
            int v = tid + l * 256;
            int r = v >> 3, c8 = v & 7;
            cpa16(&Bd[r * SA2 + c8 * 8], B + (size_t)(bm0 + r) * NPP + n0 + c8 * 8);
        }
    };

    float acc[3][4][4];
#pragma unroll
    for (int i = 0; i < 3; i++)
#pragma unroll
        for (int j = 0; j < 4; j++)
#pragma unroll
            for (int q = 0; q < 4; q++) acc[i][j][q] = 0.f;

    load_chunk(0, 0);
    CP_COMMIT();
    load_chunk(1, 64);
    CP_COMMIT();

    for (int it = 0; it < NCH; it++) {
        if (it < NCH - 1) CP_WAIT1(); else CP_WAIT0();
        __syncthreads();
        if (it + 2 < NCH) {
            load_chunk((it + 2) % 3, (it + 2) * 64);
            CP_COMMIT();
        }

        unsigned sA = (unsigned)__cvta_generic_to_shared(Ast[it % 3]);
        unsigned sB = (unsigned)__cvta_generic_to_shared(Bst[it % 3]);

#pragma unroll
        for (int kk = 0; kk < 4; kk++) {
            unsigned a[3][4], b[4][2];
#pragma unroll
            for (int i = 0; i < 3; i++) {
                int row = wc * 48 + i * 16 + rr + (g & 1) * 8;
                int ko  = kk * 16 + (g >> 1) * 8;
                unsigned ad = sA + (row * SA2 + ko) * 2;
                asm volatile("ldmatrix.sync.aligned.m8n8.x4.shared.b16 {%0,%1,%2,%3}, [%4];"
                             : "=r"(a[i][0]), "=r"(a[i][1]), "=r"(a[i][2]), "=r"(a[i][3])
                             : "r"(ad));
            }
#pragma unroll
            for (int jp = 0; jp < 2; jp++) {
                int col = wm * 32 + (jp * 2 + (g >> 1)) * 8 + rr;
                int ko  = kk * 16 + (g & 1) * 8;
                unsigned ad = sB + (col * SA2 + ko) * 2;
                asm volatile("ldmatrix.sync.aligned.m8n8.x4.shared.b16 {%0,%1,%2,%3}, [%4];"
                             : "=r"(b[jp * 2][0]), "=r"(b[jp * 2][1]),
                               "=r"(b[jp * 2 + 1][0]), "=r"(b[jp * 2 + 1][1])
                             : "r"(ad));
            }
#pragma unroll
            for (int i = 0; i < 3; i++)
#pragma unroll
                for (int j = 0; j < 4; j++) {
                    asm volatile(
                        "mma.sync.aligned.m16n8k16.row.col.f32.f16.f16.f32 "
                        "{%0,%1,%2,%3},{%4,%5,%6,%7},{%8,%9},{%0,%1,%2,%3};"
                        : "+f"(acc[i][j][0]), "+f"(acc[i][j][1]),
                          "+f"(acc[i][j][2]), "+f"(acc[i][j][3])
                        : "r"(a[i][0]), "r"(a[i][1]), "r"(a[i][2]), "r"(a[i][3]),
                          "r"(b[j][0]), "r"(b[j][1]));
                }
        }
    }

    const float invC = 1.0f / VGAIN;
    float* O = g_o + (size_t)h * HC * NPP;
#pragma unroll
    for (int i = 0; i < 3; i++) {
        int c0 = wc * 48 + i * 16 + (lane >> 2);
#pragma unroll
        for (int j = 0; j < 4; j++) {
            int m0 = bm0 + wm * 32 + j * 8 + 2 * (lane & 3);
            O[(size_t)c0 * NPP + m0]           = acc[i][j][0] * invC;
            O[(size_t)c0 * NPP + m0 + 1]       = acc[i][j][1] * invC;
            O[(size_t)(c0 + 8) * NPP + m0]     = acc[i][j][2] * invC;
            O[(size_t)(c0 + 8) * NPP + m0 + 1] = acc[i][j][3] * invC;
        }
    }
}

// ================= 8) fused fold + final 1x1 projection ====================
__global__ __launch_bounds__(256) void k_proj(const float* __restrict__ w,
                                              float* __restrict__ out) {
    __shared__ float xs[DIM][256];
    int t = threadIdx.x;
    int p0 = blockIdx.x * 256;
    int p = p0 + t;
    int y = p >> 8, x = p & 255;
    int koff = (y & 3) * 4 + (x & 3);
    int n = ((y + PADU) >> 2) * OHW + ((x + PADU) >> 2);
#pragma unroll
    for (int c = 0; c < DIM; c++) {
        int row = c * 16 + koff;
        int hh = row / HC;
        int cd = row - hh * HC;
        xs[c][t] = g_o[(size_t)(hh * HC + cd) * NPP + n];
    }
    __syncthreads();
    for (int o = 0; o < DIM; o++) {
        float acc = 0.f;
#pragma unroll
        for (int c = 0; c < DIM; c++) acc += __ldg(&w[o * DIM + c]) * xs[c][t];
        out[o * HW + p0 + t] = acc;
    }
}

// ============================================================================
extern "C" void kernel_launch(void* const* d_in, const int* in_sizes, int n_in,
                              void* d_out, int out_size) {
    const float* x      = (const float*)d_in[0];
    const float* w_qkv  = (const float*)d_in[1];
    const float* w_dw   = (const float*)d_in[2];
    const float* temp   = (const float*)d_in[3];
    const float* w_proj = (const float*)d_in[4];
    float* out = (float*)d_out;

    const int smem1 = 2 * 128 * SA1 * 2;                 // 53248
    const int smem2 = 3 * (96 + 128) * SA2 * 2;          // 96768
    cudaFuncSetAttribute(k_gemm_qk, cudaFuncAttributeMaxDynamicSharedMemorySize, smem1);
    cudaFuncSetAttribute(k_gemm_av, cudaFuncAttributeMaxDynamicSharedMemorySize, smem2);

    k_qkv_proj<<<HW / 256, 256>>>(x, w_qkv);
    k_dwconv<<<(QKVC * HW) / 256, 256>>>(w_dw);
    k_unfold_l2<<<(2 * NH * NP) / 8, 256>>>();
    k_zero_rowsum<<<(NH * NPP) / 256, 256>>>();
    {
        dim3 grid(NPP / 128, NPP / 128, NH);
        k_gemm_qk<<<grid, 256, smem1>>>(temp);
    }
    k_vscale<<<(NH * HC * NP) / 256, 256>>>();
    {
        dim3 grid(NPP / 128, NH);
        k_gemm_av<<<grid, 256, smem2>>>();
    }
    k_proj<<<HW / 256, 256>>>(w_proj, out);
}

// round 8
// speedup vs baseline: 1.1216x; 1.1216x over previous
#include <cuda_runtime.h>
#include <cuda_fp16.h>
#include <math.h>
#include <stdint.h>

// ---------------- problem constants ----------------
#define DIM     48
#define QKVC    144
#define H_IMG   256
#define W_IMG   256
#define HW      65536
#define NH      8
#define HC      96
#define OHW     66
#define NP      4356
#define NPP     4480         // padded to 35*128
#define PADU    4
#define LOG2E   1.44269504f
#define VGAIN   2048.0f

// ---------------- scratch ----------------
__device__ float  g_qkv [QKVC * HW];
__device__ float  g_dw  [QKVC * HW];
__device__ __align__(16) __half g_qt[NH * NPP * HC];   // normalized q, [h][n][c]
__device__ __align__(16) __half g_kt[NH * NPP * HC];   // normalized k, [h][m][c]
__device__ __align__(16) __half g_vh[NH * HC * NPP];   // Vs = C*v/rowsum (pad 0)
__device__ __align__(16) __half g_E [(size_t)NH * NPP * NPP]; // E^T: [h][m][n]
__device__ float  g_rowsum[NH * NPP];
__device__ float  g_o   [NH * HC * NPP];

__device__ __forceinline__ void cpa16(void* dst, const void* src) {
    unsigned d = (unsigned)__cvta_generic_to_shared(dst);
    asm volatile("cp.async.cg.shared.global [%0], [%1], 16;\n" :: "r"(d), "l"(src));
}
#define CP_COMMIT() asm volatile("cp.async.commit_group;\n")
#define CP_WAIT0()  asm volatile("cp.async.wait_group 0;\n")
#define CP_WAIT1()  asm volatile("cp.async.wait_group 1;\n")

__device__ __forceinline__ float ex2f(float x) {
    float y;
    asm("ex2.approx.f32 %0, %1;" : "=f"(y) : "f"(x));
    return y;
}

// ================= 1) qkv 1x1 projection (4-way o tiling) ==================
__global__ __launch_bounds__(256) void k_qkv_proj(const float* __restrict__ x,
                                                  const float* __restrict__ w) {
    __shared__ float xs[DIM][256];
    int t = threadIdx.x;
    int p0 = blockIdx.x * 256;
#pragma unroll
    for (int c = 0; c < DIM; c++) xs[c][t] = x[c * HW + p0 + t];
    __syncthreads();
#pragma unroll 1
    for (int o = 0; o < QKVC; o += 4) {
        const float* w0 = w + o * DIM;
        float a0 = 0.f, a1 = 0.f, a2 = 0.f, a3 = 0.f;
#pragma unroll
        for (int c = 0; c < DIM; c++) {
            float xv = xs[c][t];
            a0 = fmaf(__ldg(&w0[c]),           xv, a0);
            a1 = fmaf(__ldg(&w0[DIM + c]),     xv, a1);
            a2 = fmaf(__ldg(&w0[2 * DIM + c]), xv, a2);
            a3 = fmaf(__ldg(&w0[3 * DIM + c]), xv, a3);
        }
        g_qkv[(o + 0) * HW + p0 + t] = a0;
        g_qkv[(o + 1) * HW + p0 + t] = a1;
        g_qkv[(o + 2) * HW + p0 + t] = a2;
        g_qkv[(o + 3) * HW + p0 + t] = a3;
    }
}

// ================= 2) depthwise 3x3 ========================================
__global__ __launch_bounds__(256) void k_dwconv(const float* __restrict__ wdw) {
    int idx = blockIdx.x * 256 + threadIdx.x;
    int ch = idx >> 16;
    int p  = idx & 65535;
    int y = p >> 8, x = p & 255;
    const float* wv = wdw + ch * 9;
    const float* in = g_qkv + ch * HW;
    float acc = 0.f;
#pragma unroll
    for (int di = 0; di < 3; di++) {
        int yy = y + di - 1;
        if ((unsigned)yy >= H_IMG) continue;
#pragma unroll
        for (int dj = 0; dj < 3; dj++) {
            int xx = x + dj - 1;
            if ((unsigned)xx >= W_IMG) continue;
            acc += wv[di * 3 + dj] * in[yy * W_IMG + xx];
        }
    }
    g_dw[idx] = acc;
}

// ================= 3) fused unfold + L2-norm -> fp16; also zero rowsums ====
__global__ __launch_bounds__(256) void k_unfold_l2() {
    int gidx = blockIdx.x * 256 + threadIdx.x;
    if (gidx < NH * NPP) g_rowsum[gidx] = 0.f;
    int warp = blockIdx.x * 8 + (threadIdx.x >> 5);   // over 2*NH*NP
    int lane = threadIdx.x & 31;
    int n = warp % NP;
    int r = warp / NP;
    int h = r & 7;
    int which = r >> 3;
    int i = n / OHW, j = n - i * OHW;
    float v[3];
#pragma unroll
    for (int l = 0; l < 3; l++) {
        int cd = lane + 32 * l;
        int row = h * HC + cd;
        int c = row >> 4;
        int kk = row & 15;
        int ki = kk >> 2, kj = kk & 3;
        int y = 4 * i + ki - PADU;
        int x = 4 * j + kj - PADU;
        v[l] = 0.f;
        if ((unsigned)y < H_IMG && (unsigned)x < W_IMG)
            v[l] = g_dw[(which * DIM + c) * HW + y * W_IMG + x];
    }
    float ss = v[0] * v[0] + v[1] * v[1] + v[2] * v[2];
#pragma unroll
    for (int o = 16; o > 0; o >>= 1) ss += __shfl_xor_sync(0xffffffffu, ss, o);
    float s = 1.f / fmaxf(sqrtf(ss), 1e-12f);
    __half* dst = ((which == 0) ? g_qt : g_kt) + ((size_t)h * NPP + n) * HC;
    dst[lane]      = __float2half_rn(v[0] * s);
    dst[lane + 32] = __float2half_rn(v[1] * s);
    dst[lane + 64] = __float2half_rn(v[2] * s);
}

// ================= 5) GEMM1: E^T[m][n] = exp(t*(K_m.Q_n)-|t|), + rowsum ====
// 128(m) x 128(n), K=96 single shot. Epilogue: exp -> stage smem -> coalesced
// fp16 store of E^T + parallel column sums (over valid m) -> global atomic.
#define SA1 104
#define SE1 136
__global__ __launch_bounds__(256) void k_gemm_qk(const float* __restrict__ temp) {
    extern __shared__ __half sm[];
    __half* As = sm;                 // [128][SA1]  K rows (m)
    __half* Bs = sm + 128 * SA1;     // [128][SA1]  Q rows (n)
    __shared__ float colsum[128];
    int h = blockIdx.z;
    const __half* A = g_kt + (size_t)h * NPP * HC;
    const __half* B = g_qt + (size_t)h * NPP * HC;
    int bm0 = blockIdx.y * 128;
    int bn0 = blockIdx.x * 128;
    int tid = threadIdx.x;
    if (tid < 128) colsum[tid] = 0.f;

#pragma unroll
    for (int l = 0; l < 6; l++) {
        int v = tid + l * 256;          // < 1536
        int r = v / 12, c = v % 12;
        cpa16(&As[r * SA1 + c * 8], A + (size_t)(bm0 + r) * HC + c * 8);
        cpa16(&Bs[r * SA1 + c * 8], B + (size_t)(bn0 + r) * HC + c * 8);
    }
    CP_COMMIT();
    CP_WAIT0();
    __syncthreads();

    int warp = tid >> 5, lane = tid & 31;
    int wm = warp >> 2, wn = warp & 3;      // 2(m) x 4(n)
    int g = lane >> 3, rr = lane & 7;

    float acc[4][4][4];
#pragma unroll
    for (int i = 0; i < 4; i++)
#pragma unroll
        for (int j = 0; j < 4; j++)
#pragma unroll
            for (int q = 0; q < 4; q++) acc[i][j][q] = 0.f;

    unsigned sA = (unsigned)__cvta_generic_to_shared(As);
    unsigned sB = (unsigned)__cvta_generic_to_shared(Bs);

#pragma unroll
    for (int kk = 0; kk < 6; kk++) {
        unsigned a[4][4], b[4][2];
#pragma unroll
        for (int i = 0; i < 4; i++) {
            int row = wm * 64 + i * 16 + rr + (g & 1) * 8;
            int ko  = kk * 16 + (g >> 1) * 8;
            unsigned ad = sA + (row * SA1 + ko) * 2;
            asm volatile("ldmatrix.sync.aligned.m8n8.x4.shared.b16 {%0,%1,%2,%3}, [%4];"
                         : "=r"(a[i][0]), "=r"(a[i][1]), "=r"(a[i][2]), "=r"(a[i][3])
                         : "r"(ad));
        }
#pragma unroll
        for (int jp = 0; jp < 2; jp++) {
            int col = wn * 32 + (jp * 2 + (g >> 1)) * 8 + rr;
            int ko  = kk * 16 + (g & 1) * 8;
            unsigned ad = sB + (col * SA1 + ko) * 2;
            asm volatile("ldmatrix.sync.aligned.m8n8.x4.shared.b16 {%0,%1,%2,%3}, [%4];"
                         : "=r"(b[jp * 2][0]), "=r"(b[jp * 2][1]),
                           "=r"(b[jp * 2 + 1][0]), "=r"(b[jp * 2 + 1][1])
                         : "r"(ad));
        }
#pragma unroll
        for (int i = 0; i < 4; i++)
#pragma unroll
            for (int j = 0; j < 4; j++) {
                asm volatile(
                    "mma.sync.aligned.m16n8k16.row.col.f32.f16.f16.f32 "
                    "{%0,%1,%2,%3},{%4,%5,%6,%7},{%8,%9},{%0,%1,%2,%3};"
                    : "+f"(acc[i][j][0]), "+f"(acc[i][j][1]),
                      "+f"(acc[i][j][2]), "+f"(acc[i][j][3])
                    : "r"(a[i][0]), "r"(a[i][1]), "r"(a[i][2]), "r"(a[i][3]),
                      "r"(b[j][0]), "r"(b[j][1]));
            }
    }
    __syncthreads();   // done with As/Bs; reuse smem for staged E tile

    float t  = __ldg(&temp[h]);
    float tl = t * LOG2E;
    float ab = fabsf(t) * LOG2E;

    __half* Es = sm;   // [128][SE1]
#pragma unroll
    for (int i = 0; i < 4; i++) {
        int r0 = wm * 64 + i * 16 + (lane >> 2);
#pragma unroll
        for (int j = 0; j < 4; j++) {
            int c0 = wn * 32 + j * 8 + 2 * (lane & 3);
            float e0 = ex2f(fmaf(acc[i][j][0], tl, -ab));
            float e1 = ex2f(fmaf(acc[i][j][1], tl, -ab));
            float e2 = ex2f(fmaf(acc[i][j][2], tl, -ab));
            float e3 = ex2f(fmaf(acc[i][j][3], tl, -ab));
            *reinterpret_cast<__half2*>(&Es[r0 * SE1 + c0]) = __floats2half2_rn(e0, e1);
            *reinterpret_cast<__half2*>(&Es[(r0 + 8) * SE1 + c0]) = __floats2half2_rn(e2, e3);
        }
    }
    __syncthreads();

    // coalesced write of E^T tile
    __half* Eh = g_E + (size_t)h * NPP * NPP;
#pragma unroll
    for (int l = 0; l < 8; l++) {
        int v = tid + l * 256;          // < 2048
        int r = v >> 4, c8 = v & 15;
        reinterpret_cast<uint4*>(Eh + (size_t)(bm0 + r) * NPP + bn0)[c8] =
            reinterpret_cast<uint4*>(&Es[r * SE1])[c8];
    }

    // parallel column sums over valid m (two threads per column)
    int mlim = NP - bm0; if (mlim > 128) mlim = 128;
    {
        int col = tid & 127;
        int half = tid >> 7;            // 0 or 1
        int m0 = half * 64;
        int m1 = m0 + 64; if (m1 > mlim) m1 = mlim;
        float s = 0.f;
        for (int m = m0; m < m1; m++) s += __half2float(Es[m * SE1 + col]);
        if (s != 0.f) atomicAdd(&colsum[col], s);
    }
    __syncthreads();
    if (tid < 128) atomicAdd(&g_rowsum[h * NPP + bn0 + tid], colsum[tid]);
}

// ================= 6) fused unfold_v + scale: Vs = C*v/rowsum -> fp16 ======
__global__ __launch_bounds__(256) void k_vscale() {
    int t = blockIdx.x * 256 + threadIdx.x;  // over NH*HC*NP (exact)
    int n  = t % NP;
    int r  = t / NP;
    int cd = r % HC;
    int h  = r / HC;
    int row = h * HC + cd;
    int c  = row >> 4;
    int kk = row & 15;
    int ki = kk >> 2, kj = kk & 3;
    int i = n / OHW, j = n - i * OHW;
    int y = 4 * i + ki - PADU;
    int x = 4 * j + kj - PADU;
    float val = 0.f;
    if ((unsigned)y < H_IMG && (unsigned)x < W_IMG)
        val = g_dw[(2 * DIM + c) * HW + y * W_IMG + x];
    g_vh[(size_t)(h * HC + cd) * NPP + n] =
        __float2half_rn(__fdividef(val * VGAIN, g_rowsum[h * NPP + n]));
}

// ================= 7) GEMM2: out[c][m] = (1/C) sum_n Vs[c][n] E^T[m][n] ====
// 96(c) x 128(m) tile, k-chunk 64, 3-stage cp.async pipeline, 1 sync/iter.
#define SA2 72
#define NCH 69      // 69*64 = 4416 >= NP; last all-zero chunk skipped
__global__ __launch_bounds__(256, 2) void k_gemm_av() {
    extern __shared__ __half sm2[];
    const int STG = (96 + 128) * SA2;     // halves per stage
    __half* Ast[3] = { sm2,            sm2 + STG,            sm2 + 2 * STG };
    __half* Bst[3] = { sm2 + 96 * SA2, sm2 + STG + 96 * SA2, sm2 + 2 * STG + 96 * SA2 };

    int h = blockIdx.y;
    const __half* A = g_vh + (size_t)h * HC * NPP;
    const __half* B = g_E  + (size_t)h * NPP * NPP;
    int bm0 = blockIdx.x * 128;
    int tid = threadIdx.x;
    int warp = tid >> 5, lane = tid & 31;
    int wc = warp >> 2, wm = warp & 3;
    int g = lane >> 3, rr = lane & 7;

    auto load_chunk = [&](int stg, int n0) {
        __half* Ad = Ast[stg];
        __half* Bd = Bst[stg];
#pragma unroll
        for (int l = 0; l < 3; l++) {
            int v = tid + l * 256;
            int r = v >> 3, c8 = v & 7;
            cpa16(&Ad[r * SA2 + c8 * 8], A + (size_t)r * NPP + n0 + c8 * 8);
        }
#pragma unroll
        for (int l = 0; l < 4; l++) {
            int v = tid + l * 256;
            int r = v >> 3, c8 = v & 7;
            cpa16(&Bd[r * SA2 + c8 * 8], B + (size_t)(bm0 + r) * NPP + n0 + c8 * 8);
        }
    };

    float acc[3][4][4];
#pragma unroll
    for (int i = 0; i < 3; i++)
#pragma unroll
        for (int j = 0; j < 4; j++)
#pragma unroll
            for (int q = 0; q < 4; q++) acc[i][j][q] = 0.f;

    load_chunk(0, 0);
    CP_COMMIT();
    load_chunk(1, 64);
    CP_COMMIT();

    for (int it = 0; it < NCH; it++) {
        if (it < NCH - 1) CP_WAIT1(); else CP_WAIT0();
        __syncthreads();
        if (it + 2 < NCH) {
            load_chunk((it + 2) % 3, (it + 2) * 64);
            CP_COMMIT();
        }

        unsigned sA = (unsigned)__cvta_generic_to_shared(Ast[it % 3]);
        unsigned sB = (unsigned)__cvta_generic_to_shared(Bst[it % 3]);

#pragma unroll
        for (int kk = 0; kk < 4; kk++) {
            unsigned a[3][4], b[4][2];
#pragma unroll
            for (int i = 0; i < 3; i++) {
                int row = wc * 48 + i * 16 + rr + (g & 1) * 8;
                int ko  = kk * 16 + (g >> 1) * 8;
                unsigned ad = sA + (row * SA2 + ko) * 2;
                asm volatile("ldmatrix.sync.aligned.m8n8.x4.shared.b16 {%0,%1,%2,%3}, [%4];"
                             : "=r"(a[i][0]), "=r"(a[i][1]), "=r"(a[i][2]), "=r"(a[i][3])
                             : "r"(ad));
            }
#pragma unroll
            for (int jp = 0; jp < 2; jp++) {
                int col = wm * 32 + (jp * 2 + (g >> 1)) * 8 + rr;
                int ko  = kk * 16 + (g & 1) * 8;
                unsigned ad = sB + (col * SA2 + ko) * 2;
                asm volatile("ldmatrix.sync.aligned.m8n8.x4.shared.b16 {%0,%1,%2,%3}, [%4];"
                             : "=r"(b[jp * 2][0]), "=r"(b[jp * 2][1]),
                               "=r"(b[jp * 2 + 1][0]), "=r"(b[jp * 2 + 1][1])
                             : "r"(ad));
            }
#pragma unroll
            for (int i = 0; i < 3; i++)
#pragma unroll
                for (int j = 0; j < 4; j++) {
                    asm volatile(
                        "mma.sync.aligned.m16n8k16.row.col.f32.f16.f16.f32 "
                        "{%0,%1,%2,%3},{%4,%5,%6,%7},{%8,%9},{%0,%1,%2,%3};"
                        : "+f"(acc[i][j][0]), "+f"(acc[i][j][1]),
                          "+f"(acc[i][j][2]), "+f"(acc[i][j][3])
                        : "r"(a[i][0]), "r"(a[i][1]), "r"(a[i][2]), "r"(a[i][3]),
                          "r"(b[j][0]), "r"(b[j][1]));
                }
        }
    }

    const float invC = 1.0f / VGAIN;
    float* O = g_o + (size_t)h * HC * NPP;
#pragma unroll
    for (int i = 0; i < 3; i++) {
        int c0 = wc * 48 + i * 16 + (lane >> 2);
#pragma unroll
        for (int j = 0; j < 4; j++) {
            int m0 = bm0 + wm * 32 + j * 8 + 2 * (lane & 3);
            O[(size_t)c0 * NPP + m0]           = acc[i][j][0] * invC;
            O[(size_t)c0 * NPP + m0 + 1]       = acc[i][j][1] * invC;
            O[(size_t)(c0 + 8) * NPP + m0]     = acc[i][j][2] * invC;
            O[(size_t)(c0 + 8) * NPP + m0 + 1] = acc[i][j][3] * invC;
        }
    }
}

// ================= 8) fused fold + final 1x1 projection (4-way o tiling) ===
__global__ __launch_bounds__(256) void k_proj(const float* __restrict__ w,
                                              float* __restrict__ out) {
    __shared__ float xs[DIM][256];
    int t = threadIdx.x;
    int p0 = blockIdx.x * 256;
    int p = p0 + t;
    int y = p >> 8, x = p & 255;
    int koff = (y & 3) * 4 + (x & 3);
    int n = ((y + PADU) >> 2) * OHW + ((x + PADU) >> 2);
#pragma unroll
    for (int c = 0; c < DIM; c++) {
        int row = c * 16 + koff;
        int hh = row / HC;
        int cd = row - hh * HC;
        xs[c][t] = g_o[(size_t)(hh * HC + cd) * NPP + n];
    }
    __syncthreads();
#pragma unroll 1
    for (int o = 0; o < DIM; o += 4) {
        const float* w0 = w + o * DIM;
        float a0 = 0.f, a1 = 0.f, a2 = 0.f, a3 = 0.f;
#pragma unroll
        for (int c = 0; c < DIM; c++) {
            float xv = xs[c][t];
            a0 = fmaf(__ldg(&w0[c]),           xv, a0);
            a1 = fmaf(__ldg(&w0[DIM + c]),     xv, a1);
            a2 = fmaf(__ldg(&w0[2 * DIM + c]), xv, a2);
            a3 = fmaf(__ldg(&w0[3 * DIM + c]), xv, a3);
        }
        out[(o + 0) * HW + p0 + t] = a0;
        out[(o + 1) * HW + p0 + t] = a1;
        out[(o + 2) * HW + p0 + t] = a2;
        out[(o + 3) * HW + p0 + t] = a3;
    }
}

// ============================================================================
extern "C" void kernel_launch(void* const* d_in, const int* in_sizes, int n_in,
                              void* d_out, int out_size) {
    const float* x      = (const float*)d_in[0];
    const float* w_qkv  = (const float*)d_in[1];
    const float* w_dw   = (const float*)d_in[2];
    const float* temp   = (const float*)d_in[3];
    const float* w_proj = (const float*)d_in[4];
    float* out = (float*)d_out;

    const int smem1 = 2 * 128 * SA1 * 2;                 // 53248
    const int smem2 = 3 * (96 + 128) * SA2 * 2;          // 96768
    cudaFuncSetAttribute(k_gemm_qk, cudaFuncAttributeMaxDynamicSharedMemorySize, smem1);
    cudaFuncSetAttribute(k_gemm_av, cudaFuncAttributeMaxDynamicSharedMemorySize, smem2);

    k_qkv_proj<<<HW / 256, 256>>>(x, w_qkv);
    k_dwconv<<<(QKVC * HW) / 256, 256>>>(w_dw);
    k_unfold_l2<<<(2 * NH * NP) / 8, 256>>>();
    {
        dim3 grid(NPP / 128, NPP / 128, NH);
        k_gemm_qk<<<grid, 256, smem1>>>(temp);
    }
    k_vscale<<<(NH * HC * NP) / 256, 256>>>();
    {
        dim3 grid(NPP / 128, NH);
        k_gemm_av<<<grid, 256, smem2>>>();
    }
    k_proj<<<HW / 256, 256>>>(w_proj, out);
}